// round 10
// baseline (speedup 1.0000x reference)
#include <cuda_runtime.h>
#include <cuda_fp16.h>
#include <cstdint>

// GMEdgeConv, fp16 storage + fp16 mma.sync edge GEMM, cp.async double-buffered:
//   Stage 1 (node_kernel, fp32 math): g_UVh[n] = fp16([x@(Wt1a-Wt1b) | x@Wt1b+bt1 | x@(Wg1a-Wg1b) | x@Wg1b+bg1])
//   Stage 2 (branch_kernel): per warp, 16-edge chunks, software-pipelined:
//       cp.async gather of chunk t+1 overlaps MMA+epilogue of chunk t,
//       h1 = relu(U+V') fused into A-fragment build, D = h1 @ W2 (B frags in regs),
//       epilogue relu(D + b2) + zero-skip + filtered atomicMax segment pooling.
//   Stage 3 (final_kernel, fp32): out = relu([pool_t|pool_g] @ Wf + bf)

#define N_MAX 100000

__device__ float  g_pool[2][(size_t)N_MAX * 64];
__device__ __half g_UVh[(size_t)N_MAX * 256];

// D += A(16x16 f16) @ B(16x8 f16), fp32 accum
__device__ __forceinline__ void mma_f16(float* c, const uint32_t* a,
                                        uint32_t b0, uint32_t b1) {
    asm volatile(
        "mma.sync.aligned.m16n8k16.row.col.f32.f16.f16.f32 "
        "{%0,%1,%2,%3}, {%4,%5,%6,%7}, {%8,%9}, {%0,%1,%2,%3};\n"
        : "+f"(c[0]), "+f"(c[1]), "+f"(c[2]), "+f"(c[3])
        : "r"(a[0]), "r"(a[1]), "r"(a[2]), "r"(a[3]), "r"(b0), "r"(b1));
}

__device__ __forceinline__ uint32_t hrelu_add(uint32_t u, uint32_t v) {
    __half2 z = __float2half2_rn(0.f);
    __half2 r = __hmax2(__hadd2(*(__half2*)&u, *(__half2*)&v), z);
    return *(uint32_t*)&r;
}

__device__ __forceinline__ void cp_async16(void* smem_dst, const void* gmem_src) {
    uint32_t s = (uint32_t)__cvta_generic_to_shared(smem_dst);
    asm volatile("cp.async.cg.shared.global [%0], [%1], 16;" :: "r"(s), "l"(gmem_src));
}
#define CP_COMMIT() asm volatile("cp.async.commit_group;" ::: "memory")
#define CP_WAIT1()  asm volatile("cp.async.wait_group 1;" ::: "memory")

// ---------------------------------------------------------------------------
// Stage 1: node projections (fp32 math, fp16 store), b1 folded into V columns.
// ---------------------------------------------------------------------------
__global__ __launch_bounds__(512, 1)
void node_kernel(const float* __restrict__ x,
                 const float* __restrict__ Wt1, const float* __restrict__ Wg1,
                 const float* __restrict__ bt1, const float* __restrict__ bg1,
                 int nN)
{
    extern __shared__ float sm[];
    float* Wc = sm;              // 64 x 260 (cols: Ut|Vt|Ug|Vg)
    float* As = Wc + 64 * 260;   // 128 x 68

    const int tid = threadIdx.x;
    const int tx  = tid & 31;
    const int ty  = tid >> 5;

    for (int idx = tid; idx < 64 * 256; idx += 512) {
        int k = idx >> 8, c = idx & 255;
        float v;
        if (c < 64)        v = Wt1[k * 64 + c] - Wt1[(64 + k) * 64 + c];
        else if (c < 128)  v = Wt1[(64 + k) * 64 + (c - 64)];
        else if (c < 192)  v = Wg1[k * 64 + (c - 128)] - Wg1[(64 + k) * 64 + (c - 128)];
        else               v = Wg1[(64 + k) * 64 + (c - 192)];
        Wc[k * 260 + c] = v;
    }

    const int base = blockIdx.x * 128;
    for (int idx = tid; idx < 128 * 16; idx += 512) {
        int nd = idx >> 4, q = idx & 15;
        float4 v = make_float4(0.f, 0.f, 0.f, 0.f);
        if (base + nd < nN) v = *(const float4*)(x + (size_t)(base + nd) * 64 + 4 * q);
        *(float4*)(As + nd * 68 + 4 * q) = v;
    }
    __syncthreads();

    #pragma unroll
    for (int p = 0; p < 2; p++) {
        const int c = p * 128 + 4 * tx;
        float acc[8][4];
        #pragma unroll
        for (int ii = 0; ii < 8; ii++)
            #pragma unroll
            for (int j = 0; j < 4; j++) acc[ii][j] = 0.f;

        #pragma unroll 4
        for (int k = 0; k < 64; k += 4) {
            float4 w0 = *(const float4*)(Wc + (k + 0) * 260 + c);
            float4 w1 = *(const float4*)(Wc + (k + 1) * 260 + c);
            float4 w2 = *(const float4*)(Wc + (k + 2) * 260 + c);
            float4 w3 = *(const float4*)(Wc + (k + 3) * 260 + c);
            #pragma unroll
            for (int ii = 0; ii < 8; ii++) {
                float4 a = *(const float4*)(As + (8 * ty + ii) * 68 + k);
                acc[ii][0] += a.x * w0.x + a.y * w1.x + a.z * w2.x + a.w * w3.x;
                acc[ii][1] += a.x * w0.y + a.y * w1.y + a.z * w2.y + a.w * w3.y;
                acc[ii][2] += a.x * w0.z + a.y * w1.z + a.z * w2.z + a.w * w3.z;
                acc[ii][3] += a.x * w0.w + a.y * w1.w + a.z * w2.w + a.w * w3.w;
            }
        }
        float4 bv = make_float4(0.f, 0.f, 0.f, 0.f);
        if (4 * tx >= 64) {
            const float* bp = (p ? bg1 : bt1) + (4 * tx - 64);
            bv = *(const float4*)bp;
        }
        #pragma unroll
        for (int ii = 0; ii < 8; ii++) {
            int node = base + 8 * ty + ii;
            if (node < nN) {
                __half2 h0 = __float22half2_rn(make_float2(acc[ii][0] + bv.x,
                                                           acc[ii][1] + bv.y));
                __half2 h1 = __float22half2_rn(make_float2(acc[ii][2] + bv.z,
                                                           acc[ii][3] + bv.w));
                uint2 pk;
                pk.x = *(uint32_t*)&h0;
                pk.y = *(uint32_t*)&h1;
                *(uint2*)(g_UVh + (size_t)node * 256 + c) = pk;
            }
        }
    }
}

// ---------------------------------------------------------------------------
// Stage 2: pipelined warp-level fp16 MMA edge GEMM + segment max.
// grid (148, 2): y = branch. 2 CTAs/SM, 8 warps/CTA, warp = 16-edge chunk.
// smem: W2T 9216B + b2s 256B + per-warp double-buffered UV (2x2x2304B) = 83200B.
// ---------------------------------------------------------------------------
__global__ __launch_bounds__(256, 2)
void branch_kernel(const int* __restrict__ ei_t, const int* __restrict__ ei_g,
                   const float* __restrict__ Wt2, const float* __restrict__ Wg2,
                   const float* __restrict__ bt2, const float* __restrict__ bg2,
                   int nE)
{
    extern __shared__ __align__(16) __half smB[];
    __half* W2T = smB;                         // [n][k], stride 72 (4608 halves)
    float*  b2s = (float*)(smB + 4608);        // 64 floats (128 halves)
    __half* UVb = smB + 4736;                  // 8 warps x 2 buf x 2 seg x 1152

    const int tid  = threadIdx.x;
    const int warp = tid >> 5;
    const int lane = tid & 31;
    const int qr   = lane & 3;      // threadID_in_group
    const int gp   = lane >> 2;     // groupID
    const int br   = blockIdx.y;

    const int*   ei = br ? ei_g : ei_t;
    const float* W2 = br ? Wg2 : Wt2;
    const float* b2 = br ? bg2 : bt2;
    float* pool = g_pool[br];

    // Stage W2^T (fp16, [n*72+k]) and b2.
    for (int idx = tid; idx < 64 * 64; idx += 256) {
        int k = idx >> 6, n = idx & 63;
        W2T[n * 72 + k] = __float2half_rn(W2[idx]);
    }
    if (tid < 64) b2s[tid] = b2[tid];
    __syncthreads();

    // Hoist B fragments to registers (chunk-invariant): 64 regs.
    const uint32_t* W2T32 = (const uint32_t*)W2T;
    uint32_t Bf[4][8][2];
    #pragma unroll
    for (int kt = 0; kt < 4; kt++)
        #pragma unroll
        for (int nt = 0; nt < 8; nt++) {
            Bf[kt][nt][0] = W2T32[(nt * 8 + gp) * 36 + kt * 8 + qr];
            Bf[kt][nt][1] = W2T32[(nt * 8 + gp) * 36 + kt * 8 + qr + 4];
        }

    __half* myUV = UVb + warp * 4608;          // [buf][seg][16*72]
    const int grow = lane >> 3;                // row-group within coalesced copy
    const int qb   = lane & 7;                 // 16B chunk within 128B row

    const int nChunks = (nE + 15) >> 4;
    const int STRIDE = gridDim.x * 8;

    // --- helpers as lambdas ---
    auto load_idx = [&](int ch) -> int {
        int e0 = ch << 4;
        int v;
        if (lane < 16) v = (e0 + lane < nE) ? __ldcs(ei + e0 + lane) : -1;
        else           v = (e0 + lane - 16 < nE) ? __ldcs(ei + nE + e0 + lane - 16) : 0;
        return v;
    };
    auto gather = [&](int buf, int iv) {
        #pragma unroll
        for (int seg = 0; seg < 2; seg++) {
            __half* dstS = myUV + buf * 2304 + seg * 1152;
            #pragma unroll
            for (int gg = 0; gg < 4; gg++) {
                int e = gg * 4 + grow;
                int idx = __shfl_sync(0xFFFFFFFFu, iv, e + seg * 16);
                idx = idx < 0 ? 0 : idx;
                const __half* src = g_UVh + (size_t)idx * 256 + br * 128
                                  + seg * 64 + qb * 8;
                cp_async16(dstS + e * 72 + qb * 8, src);
            }
        }
    };

    int ch = blockIdx.x * 8 + warp;
    if (ch < nChunks) {
        int iv = load_idx(ch);
        gather(0, iv);
        CP_COMMIT();

        int chn = ch + STRIDE;
        bool hasn = chn < nChunks;
        int ivn = hasn ? load_idx(chn) : 0;
        int buf = 0;

        while (true) {
            // issue next chunk's gather before computing current
            if (hasn) gather(buf ^ 1, ivn);
            CP_COMMIT();
            CP_WAIT1();          // current buf's group complete (1 pending allowed)
            __syncwarp();

            // ---- compute chunk (buf, iv) ----
            const uint32_t* Uw = (const uint32_t*)(myUV + buf * 2304);
            const uint32_t* Vw = (const uint32_t*)(myUV + buf * 2304 + 1152);

            float acc[8][4];
            #pragma unroll
            for (int nt = 0; nt < 8; nt++)
                #pragma unroll
                for (int q = 0; q < 4; q++) acc[nt][q] = 0.f;

            #pragma unroll
            for (int kt = 0; kt < 4; kt++) {
                const int c = kt * 8 + qr;
                uint32_t a[4];
                a[0] = hrelu_add(Uw[gp * 36 + c],           Vw[gp * 36 + c]);
                a[1] = hrelu_add(Uw[(gp + 8) * 36 + c],     Vw[(gp + 8) * 36 + c]);
                a[2] = hrelu_add(Uw[gp * 36 + c + 4],       Vw[gp * 36 + c + 4]);
                a[3] = hrelu_add(Uw[(gp + 8) * 36 + c + 4], Vw[(gp + 8) * 36 + c + 4]);
                #pragma unroll
                for (int nt = 0; nt < 8; nt++)
                    mma_f16(acc[nt], a, Bf[kt][nt][0], Bf[kt][nt][1]);
            }

            // ---- epilogue: relu(D + b2), zero-skip + filtered segment-max ----
            int i1 = __shfl_sync(0xFFFFFFFFu, iv, gp);
            int i2 = __shfl_sync(0xFFFFFFFFu, iv, gp + 8);
            if (i1 >= 0) {
                float* pr = pool + (size_t)i1 * 64 + qr * 2;
                #pragma unroll
                for (int nt = 0; nt < 8; nt++) {
                    float2 bb = *(const float2*)(b2s + nt * 8 + qr * 2);
                    float va = fmaxf(acc[nt][0] + bb.x, 0.f);
                    float vb = fmaxf(acc[nt][1] + bb.y, 0.f);
                    if (va > 0.f || vb > 0.f) {   // pool >= 0: zero never wins
                        float2 cur = __ldcg((const float2*)(pr + nt * 8));
                        // pool only grows; stale read >= v proves final max >= v.
                        if (va > cur.x) atomicMax((int*)(pr + nt * 8),     __float_as_int(va));
                        if (vb > cur.y) atomicMax((int*)(pr + nt * 8 + 1), __float_as_int(vb));
                    }
                }
            }
            if (i2 >= 0) {
                float* pr = pool + (size_t)i2 * 64 + qr * 2;
                #pragma unroll
                for (int nt = 0; nt < 8; nt++) {
                    float2 bb = *(const float2*)(b2s + nt * 8 + qr * 2);
                    float va = fmaxf(acc[nt][2] + bb.x, 0.f);
                    float vb = fmaxf(acc[nt][3] + bb.y, 0.f);
                    if (va > 0.f || vb > 0.f) {
                        float2 cur = __ldcg((const float2*)(pr + nt * 8));
                        if (va > cur.x) atomicMax((int*)(pr + nt * 8),     __float_as_int(va));
                        if (vb > cur.y) atomicMax((int*)(pr + nt * 8 + 1), __float_as_int(vb));
                    }
                }
            }

            if (!hasn) break;
            ch = chn; iv = ivn;
            chn += STRIDE;
            bool h2 = chn < nChunks;
            if (h2) ivn = load_idx(chn);
            hasn = h2;
            buf ^= 1;
        }
    }
}

// ---------------------------------------------------------------------------
// Stage 3: out = relu([pool_t | pool_g] @ Wf + bf)   (fp32)
// ---------------------------------------------------------------------------
__global__ __launch_bounds__(256, 1)
void final_kernel(const float* __restrict__ Wf, const float* __restrict__ bf,
                  float* __restrict__ out, int nN)
{
    extern __shared__ float sm[];
    float* Wfs = sm;                // 128 x 64
    float* Ns  = Wfs + 128 * 64;    // 128 x 132

    const int tid = threadIdx.x;
    const int tx  = tid & 15;
    const int ty  = tid >> 4;

    for (int idx = tid; idx < 128 * 64; idx += 256) Wfs[idx] = Wf[idx];
    const float4 bfv = *(const float4*)(bf + 4 * tx);

    const int base = blockIdx.x * 128;
    for (int idx = tid; idx < 128 * 16; idx += 256) {
        int nd = idx >> 4, q = idx & 15;
        float4 a = make_float4(0.f, 0.f, 0.f, 0.f);
        float4 b = make_float4(0.f, 0.f, 0.f, 0.f);
        if (base + nd < nN) {
            a = *(const float4*)(g_pool[0] + (size_t)(base + nd) * 64 + 4 * q);
            b = *(const float4*)(g_pool[1] + (size_t)(base + nd) * 64 + 4 * q);
        }
        *(float4*)(Ns + nd * 132 + 4 * q) = a;
        *(float4*)(Ns + nd * 132 + 64 + 4 * q) = b;
    }
    __syncthreads();

    float acc[8][4];
    #pragma unroll
    for (int ii = 0; ii < 8; ii++)
        #pragma unroll
        for (int j = 0; j < 4; j++) acc[ii][j] = 0.f;

    #pragma unroll 4
    for (int k = 0; k < 128; k += 4) {
        float4 w0 = *(const float4*)(Wfs + (k + 0) * 64 + 4 * tx);
        float4 w1 = *(const float4*)(Wfs + (k + 1) * 64 + 4 * tx);
        float4 w2 = *(const float4*)(Wfs + (k + 2) * 64 + 4 * tx);
        float4 w3 = *(const float4*)(Wfs + (k + 3) * 64 + 4 * tx);
        #pragma unroll
        for (int ii = 0; ii < 8; ii++) {
            float4 a = *(const float4*)(Ns + (8 * ty + ii) * 132 + k);
            acc[ii][0] += a.x * w0.x + a.y * w1.x + a.z * w2.x + a.w * w3.x;
            acc[ii][1] += a.x * w0.y + a.y * w1.y + a.z * w2.y + a.w * w3.y;
            acc[ii][2] += a.x * w0.z + a.y * w1.z + a.z * w2.z + a.w * w3.z;
            acc[ii][3] += a.x * w0.w + a.y * w1.w + a.z * w2.w + a.w * w3.w;
        }
    }

    #pragma unroll
    for (int ii = 0; ii < 8; ii++) {
        int node = base + 8 * ty + ii;
        if (node < nN) {
            float4 o;
            o.x = fmaxf(acc[ii][0] + bfv.x, 0.f);
            o.y = fmaxf(acc[ii][1] + bfv.y, 0.f);
            o.z = fmaxf(acc[ii][2] + bfv.z, 0.f);
            o.w = fmaxf(acc[ii][3] + bfv.w, 0.f);
            *(float4*)(out + (size_t)node * 64 + 4 * tx) = o;
        }
    }
}

// ---------------------------------------------------------------------------
extern "C" void kernel_launch(void* const* d_in, const int* in_sizes, int n_in,
                              void* d_out, int out_size)
{
    const float* x   = (const float*)d_in[0];
    const int*   eit = (const int*)d_in[1];
    const int*   eig = (const int*)d_in[2];
    const float* Wt1 = (const float*)d_in[3];
    const float* bt1 = (const float*)d_in[4];
    const float* Wt2 = (const float*)d_in[5];
    const float* bt2 = (const float*)d_in[6];
    const float* Wg1 = (const float*)d_in[7];
    const float* bg1 = (const float*)d_in[8];
    const float* Wg2 = (const float*)d_in[9];
    const float* bg2 = (const float*)d_in[10];
    const float* Wf  = (const float*)d_in[11];
    const float* bf  = (const float*)d_in[12];
    float* out = (float*)d_out;

    const int nN = in_sizes[0] / 64;
    const int nE = in_sizes[1] / 2;

    void* poolPtr = nullptr;
    cudaGetSymbolAddress(&poolPtr, g_pool);
    cudaMemsetAsync(poolPtr, 0, sizeof(float) * 2 * (size_t)N_MAX * 64, 0);

    const int smemN = (64 * 260 + 128 * 68) * 4;
    cudaFuncSetAttribute(node_kernel,
                         cudaFuncAttributeMaxDynamicSharedMemorySize, smemN);
    node_kernel<<<(nN + 127) / 128, 512, smemN>>>(x, Wt1, Wg1, bt1, bg1, nN);

    const int smemB = (4608 + 128 + 8 * 4608) * 2;   // 83200 B
    cudaFuncSetAttribute(branch_kernel,
                         cudaFuncAttributeMaxDynamicSharedMemorySize, smemB);
    dim3 gridB(148, 2);
    branch_kernel<<<gridB, 256, smemB>>>(eit, eig, Wt2, Wg2, bt2, bg2, nE);

    const int smemF = (128 * 64 + 128 * 132) * 4;
    cudaFuncSetAttribute(final_kernel,
                         cudaFuncAttributeMaxDynamicSharedMemorySize, smemF);
    final_kernel<<<(nN + 127) / 128, 256, smemF>>>(Wf, bf, out, nN);
}

// round 12
// speedup vs baseline: 1.1661x; 1.1661x over previous
#include <cuda_runtime.h>
#include <cuda_fp16.h>
#include <cstdint>

// GMEdgeConv, fp16 storage + fp16 mma.sync edge GEMM, cp.async double-buffered
// WITHOUT register pressure (B fragments stay in SMEM; R10's hoist caused spills):
//   Stage 1 (node_kernel, fp32 math): g_UVh[n] = fp16([x@(Wt1a-Wt1b) | x@Wt1b+bt1 | x@(Wg1a-Wg1b) | x@Wg1b+bg1])
//   Stage 2 (branch_kernel): 10 warps/CTA, 2 CTAs/SM; per warp, 16-edge chunks:
//       cp.async gather of chunk t+1 overlaps MMA+epilogue of chunk t,
//       h1 = relu(U+V') fused into A-fragment build, D = h1 @ W2 (B frags from SMEM),
//       epilogue relu(D + b2) + zero-skip + filtered atomicMax segment pooling.
//   Stage 3 (final_kernel, fp32): out = relu([pool_t|pool_g] @ Wf + bf)

#define N_MAX 100000

__device__ float  g_pool[2][(size_t)N_MAX * 64];
__device__ __half g_UVh[(size_t)N_MAX * 256];

// D += A(16x16 f16) @ B(16x8 f16), fp32 accum
__device__ __forceinline__ void mma_f16(float* c, const uint32_t* a,
                                        uint32_t b0, uint32_t b1) {
    asm volatile(
        "mma.sync.aligned.m16n8k16.row.col.f32.f16.f16.f32 "
        "{%0,%1,%2,%3}, {%4,%5,%6,%7}, {%8,%9}, {%0,%1,%2,%3};\n"
        : "+f"(c[0]), "+f"(c[1]), "+f"(c[2]), "+f"(c[3])
        : "r"(a[0]), "r"(a[1]), "r"(a[2]), "r"(a[3]), "r"(b0), "r"(b1));
}

__device__ __forceinline__ uint32_t hrelu_add(uint32_t u, uint32_t v) {
    __half2 z = __float2half2_rn(0.f);
    __half2 r = __hmax2(__hadd2(*(__half2*)&u, *(__half2*)&v), z);
    return *(uint32_t*)&r;
}

__device__ __forceinline__ void cp_async16(void* smem_dst, const void* gmem_src) {
    uint32_t s = (uint32_t)__cvta_generic_to_shared(smem_dst);
    asm volatile("cp.async.cg.shared.global [%0], [%1], 16;" :: "r"(s), "l"(gmem_src));
}
#define CP_COMMIT() asm volatile("cp.async.commit_group;" ::: "memory")
#define CP_WAIT1()  asm volatile("cp.async.wait_group 1;" ::: "memory")

// ---------------------------------------------------------------------------
// Stage 1: node projections (fp32 math, fp16 store), b1 folded into V columns.
// ---------------------------------------------------------------------------
__global__ __launch_bounds__(512, 1)
void node_kernel(const float* __restrict__ x,
                 const float* __restrict__ Wt1, const float* __restrict__ Wg1,
                 const float* __restrict__ bt1, const float* __restrict__ bg1,
                 int nN)
{
    extern __shared__ float sm[];
    float* Wc = sm;              // 64 x 260 (cols: Ut|Vt|Ug|Vg)
    float* As = Wc + 64 * 260;   // 128 x 68

    const int tid = threadIdx.x;
    const int tx  = tid & 31;
    const int ty  = tid >> 5;

    for (int idx = tid; idx < 64 * 256; idx += 512) {
        int k = idx >> 8, c = idx & 255;
        float v;
        if (c < 64)        v = Wt1[k * 64 + c] - Wt1[(64 + k) * 64 + c];
        else if (c < 128)  v = Wt1[(64 + k) * 64 + (c - 64)];
        else if (c < 192)  v = Wg1[k * 64 + (c - 128)] - Wg1[(64 + k) * 64 + (c - 128)];
        else               v = Wg1[(64 + k) * 64 + (c - 192)];
        Wc[k * 260 + c] = v;
    }

    const int base = blockIdx.x * 128;
    for (int idx = tid; idx < 128 * 16; idx += 512) {
        int nd = idx >> 4, q = idx & 15;
        float4 v = make_float4(0.f, 0.f, 0.f, 0.f);
        if (base + nd < nN) v = *(const float4*)(x + (size_t)(base + nd) * 64 + 4 * q);
        *(float4*)(As + nd * 68 + 4 * q) = v;
    }
    __syncthreads();

    #pragma unroll
    for (int p = 0; p < 2; p++) {
        const int c = p * 128 + 4 * tx;
        float acc[8][4];
        #pragma unroll
        for (int ii = 0; ii < 8; ii++)
            #pragma unroll
            for (int j = 0; j < 4; j++) acc[ii][j] = 0.f;

        #pragma unroll 4
        for (int k = 0; k < 64; k += 4) {
            float4 w0 = *(const float4*)(Wc + (k + 0) * 260 + c);
            float4 w1 = *(const float4*)(Wc + (k + 1) * 260 + c);
            float4 w2 = *(const float4*)(Wc + (k + 2) * 260 + c);
            float4 w3 = *(const float4*)(Wc + (k + 3) * 260 + c);
            #pragma unroll
            for (int ii = 0; ii < 8; ii++) {
                float4 a = *(const float4*)(As + (8 * ty + ii) * 68 + k);
                acc[ii][0] += a.x * w0.x + a.y * w1.x + a.z * w2.x + a.w * w3.x;
                acc[ii][1] += a.x * w0.y + a.y * w1.y + a.z * w2.y + a.w * w3.y;
                acc[ii][2] += a.x * w0.z + a.y * w1.z + a.z * w2.z + a.w * w3.z;
                acc[ii][3] += a.x * w0.w + a.y * w1.w + a.z * w2.w + a.w * w3.w;
            }
        }
        float4 bv = make_float4(0.f, 0.f, 0.f, 0.f);
        if (4 * tx >= 64) {
            const float* bp = (p ? bg1 : bt1) + (4 * tx - 64);
            bv = *(const float4*)bp;
        }
        #pragma unroll
        for (int ii = 0; ii < 8; ii++) {
            int node = base + 8 * ty + ii;
            if (node < nN) {
                __half2 h0 = __float22half2_rn(make_float2(acc[ii][0] + bv.x,
                                                           acc[ii][1] + bv.y));
                __half2 h1 = __float22half2_rn(make_float2(acc[ii][2] + bv.z,
                                                           acc[ii][3] + bv.w));
                uint2 pk;
                pk.x = *(uint32_t*)&h0;
                pk.y = *(uint32_t*)&h1;
                *(uint2*)(g_UVh + (size_t)node * 256 + c) = pk;
            }
        }
    }
}

// ---------------------------------------------------------------------------
// Stage 2: pipelined warp-level fp16 MMA edge GEMM + segment max.
// grid (148, 2): y = branch. 2 CTAs/SM, 10 warps/CTA (20 warps/SM),
// warp = 16-edge chunk, double-buffered cp.async gather, B frags from SMEM.
// smem/CTA: W2T 9216B + 10 warps x (2 buf x 2 seg x 2304B) = 101376B.
// ---------------------------------------------------------------------------
#define BWARPS 10
__global__ __launch_bounds__(32 * BWARPS, 2)
void branch_kernel(const int* __restrict__ ei_t, const int* __restrict__ ei_g,
                   const float* __restrict__ Wt2, const float* __restrict__ Wg2,
                   const float* __restrict__ bt2, const float* __restrict__ bg2,
                   int nE)
{
    extern __shared__ __align__(16) __half smB[];
    __half* W2T = smB;                         // [n][k], stride 72 (4608 halves)
    __half* UVb = smB + 4608;                  // BWARPS x 2 buf x 2 seg x 1152

    const int tid  = threadIdx.x;
    const int warp = tid >> 5;
    const int lane = tid & 31;
    const int qr   = lane & 3;      // threadID_in_group
    const int gp   = lane >> 2;     // groupID
    const int br   = blockIdx.y;

    const int*   ei = br ? ei_g : ei_t;
    const float* W2 = br ? Wg2 : Wt2;
    const float* b2 = br ? bg2 : bt2;
    float* pool = g_pool[br];

    // Stage W2^T: W2 is [k][n] row-major; store W2T[n*72 + k] (fp16).
    for (int idx = tid; idx < 64 * 64; idx += 32 * BWARPS) {
        int k = idx >> 6, n = idx & 63;
        W2T[n * 72 + k] = __float2half_rn(W2[idx]);
    }
    __syncthreads();

    const uint32_t* W2T32 = (const uint32_t*)W2T;

    // preload b2 pairs for this thread's fragment columns (regs, from global)
    float2 b2v[8];
    #pragma unroll
    for (int nt = 0; nt < 8; nt++)
        b2v[nt] = *(const float2*)(b2 + nt * 8 + qr * 2);

    __half* myUV = UVb + warp * 4608;          // [buf][seg][16*72]
    const int grow = lane >> 3;                // row-group within coalesced copy
    const int qb   = lane & 7;                 // 16B chunk within 128B row

    const int nChunks = (nE + 15) >> 4;
    const int STRIDE = gridDim.x * BWARPS;

    auto load_idx = [&](int ch) -> int {
        int e0 = ch << 4;
        int v;
        if (lane < 16) v = (e0 + lane < nE) ? __ldcs(ei + e0 + lane) : -1;
        else           v = (e0 + lane - 16 < nE) ? __ldcs(ei + nE + e0 + lane - 16) : 0;
        return v;
    };
    auto gather = [&](int buf, int iv) {
        #pragma unroll
        for (int seg = 0; seg < 2; seg++) {
            __half* dstS = myUV + buf * 2304 + seg * 1152;
            #pragma unroll
            for (int gg = 0; gg < 4; gg++) {
                int e = gg * 4 + grow;
                int idx = __shfl_sync(0xFFFFFFFFu, iv, e + seg * 16);
                idx = idx < 0 ? 0 : idx;
                const __half* src = g_UVh + (size_t)idx * 256 + br * 128
                                  + seg * 64 + qb * 8;
                cp_async16(dstS + e * 72 + qb * 8, src);
            }
        }
    };

    int ch = blockIdx.x * BWARPS + warp;
    if (ch < nChunks) {
        int iv = load_idx(ch);
        gather(0, iv);
        CP_COMMIT();

        int chn = ch + STRIDE;
        bool hasn = chn < nChunks;
        int ivn = hasn ? load_idx(chn) : 0;
        int buf = 0;

        while (true) {
            // issue next chunk's gather before computing current
            if (hasn) gather(buf ^ 1, ivn);
            CP_COMMIT();
            CP_WAIT1();          // current buf's group complete (1 pending allowed)
            __syncwarp();

            // ---- compute chunk (buf, iv) ----
            const uint32_t* Uw = (const uint32_t*)(myUV + buf * 2304);
            const uint32_t* Vw = (const uint32_t*)(myUV + buf * 2304 + 1152);

            float acc[8][4];
            #pragma unroll
            for (int nt = 0; nt < 8; nt++)
                #pragma unroll
                for (int q = 0; q < 4; q++) acc[nt][q] = 0.f;

            #pragma unroll
            for (int kt = 0; kt < 4; kt++) {
                const int c = kt * 8 + qr;
                uint32_t a[4];
                a[0] = hrelu_add(Uw[gp * 36 + c],           Vw[gp * 36 + c]);
                a[1] = hrelu_add(Uw[(gp + 8) * 36 + c],     Vw[(gp + 8) * 36 + c]);
                a[2] = hrelu_add(Uw[gp * 36 + c + 4],       Vw[gp * 36 + c + 4]);
                a[3] = hrelu_add(Uw[(gp + 8) * 36 + c + 4], Vw[(gp + 8) * 36 + c + 4]);
                #pragma unroll
                for (int nt = 0; nt < 8; nt++) {
                    uint32_t b0 = W2T32[(nt * 8 + gp) * 36 + kt * 8 + qr];
                    uint32_t b1 = W2T32[(nt * 8 + gp) * 36 + kt * 8 + qr + 4];
                    mma_f16(acc[nt], a, b0, b1);
                }
            }
            __syncwarp();   // all UV reads done before next iteration's STS

            // ---- epilogue: relu(D + b2), zero-skip + filtered segment-max ----
            int i1 = __shfl_sync(0xFFFFFFFFu, iv, gp);
            int i2 = __shfl_sync(0xFFFFFFFFu, iv, gp + 8);
            if (i1 >= 0) {
                float* pr = pool + (size_t)i1 * 64 + qr * 2;
                #pragma unroll
                for (int nt = 0; nt < 8; nt++) {
                    float va = fmaxf(acc[nt][0] + b2v[nt].x, 0.f);
                    float vb = fmaxf(acc[nt][1] + b2v[nt].y, 0.f);
                    if (va > 0.f || vb > 0.f) {   // pool >= 0: zero never wins
                        float2 cur = __ldcg((const float2*)(pr + nt * 8));
                        // pool only grows; stale read >= v proves final max >= v.
                        if (va > cur.x) atomicMax((int*)(pr + nt * 8),     __float_as_int(va));
                        if (vb > cur.y) atomicMax((int*)(pr + nt * 8 + 1), __float_as_int(vb));
                    }
                }
            }
            if (i2 >= 0) {
                float* pr = pool + (size_t)i2 * 64 + qr * 2;
                #pragma unroll
                for (int nt = 0; nt < 8; nt++) {
                    float va = fmaxf(acc[nt][2] + b2v[nt].x, 0.f);
                    float vb = fmaxf(acc[nt][3] + b2v[nt].y, 0.f);
                    if (va > 0.f || vb > 0.f) {
                        float2 cur = __ldcg((const float2*)(pr + nt * 8));
                        if (va > cur.x) atomicMax((int*)(pr + nt * 8),     __float_as_int(va));
                        if (vb > cur.y) atomicMax((int*)(pr + nt * 8 + 1), __float_as_int(vb));
                    }
                }
            }

            if (!hasn) break;
            ch = chn; iv = ivn;
            chn += STRIDE;
            bool h2 = chn < nChunks;
            if (h2) ivn = load_idx(chn);
            hasn = h2;
            buf ^= 1;
        }
    }
}

// ---------------------------------------------------------------------------
// Stage 3: out = relu([pool_t | pool_g] @ Wf + bf)   (fp32)
// ---------------------------------------------------------------------------
__global__ __launch_bounds__(256, 1)
void final_kernel(const float* __restrict__ Wf, const float* __restrict__ bf,
                  float* __restrict__ out, int nN)
{
    extern __shared__ float sm[];
    float* Wfs = sm;                // 128 x 64
    float* Ns  = Wfs + 128 * 64;    // 128 x 132

    const int tid = threadIdx.x;
    const int tx  = tid & 15;
    const int ty  = tid >> 4;

    for (int idx = tid; idx < 128 * 64; idx += 256) Wfs[idx] = Wf[idx];
    const float4 bfv = *(const float4*)(bf + 4 * tx);

    const int base = blockIdx.x * 128;
    for (int idx = tid; idx < 128 * 16; idx += 256) {
        int nd = idx >> 4, q = idx & 15;
        float4 a = make_float4(0.f, 0.f, 0.f, 0.f);
        float4 b = make_float4(0.f, 0.f, 0.f, 0.f);
        if (base + nd < nN) {
            a = *(const float4*)(g_pool[0] + (size_t)(base + nd) * 64 + 4 * q);
            b = *(const float4*)(g_pool[1] + (size_t)(base + nd) * 64 + 4 * q);
        }
        *(float4*)(Ns + nd * 132 + 4 * q) = a;
        *(float4*)(Ns + nd * 132 + 64 + 4 * q) = b;
    }
    __syncthreads();

    float acc[8][4];
    #pragma unroll
    for (int ii = 0; ii < 8; ii++)
        #pragma unroll
        for (int j = 0; j < 4; j++) acc[ii][j] = 0.f;

    #pragma unroll 4
    for (int k = 0; k < 128; k += 4) {
        float4 w0 = *(const float4*)(Wfs + (k + 0) * 64 + 4 * tx);
        float4 w1 = *(const float4*)(Wfs + (k + 1) * 64 + 4 * tx);
        float4 w2 = *(const float4*)(Wfs + (k + 2) * 64 + 4 * tx);
        float4 w3 = *(const float4*)(Wfs + (k + 3) * 64 + 4 * tx);
        #pragma unroll
        for (int ii = 0; ii < 8; ii++) {
            float4 a = *(const float4*)(Ns + (8 * ty + ii) * 132 + k);
            acc[ii][0] += a.x * w0.x + a.y * w1.x + a.z * w2.x + a.w * w3.x;
            acc[ii][1] += a.x * w0.y + a.y * w1.y + a.z * w2.y + a.w * w3.y;
            acc[ii][2] += a.x * w0.z + a.y * w1.z + a.z * w2.z + a.w * w3.z;
            acc[ii][3] += a.x * w0.w + a.y * w1.w + a.z * w2.w + a.w * w3.w;
        }
    }

    #pragma unroll
    for (int ii = 0; ii < 8; ii++) {
        int node = base + 8 * ty + ii;
        if (node < nN) {
            float4 o;
            o.x = fmaxf(acc[ii][0] + bfv.x, 0.f);
            o.y = fmaxf(acc[ii][1] + bfv.y, 0.f);
            o.z = fmaxf(acc[ii][2] + bfv.z, 0.f);
            o.w = fmaxf(acc[ii][3] + bfv.w, 0.f);
            *(float4*)(out + (size_t)node * 64 + 4 * tx) = o;
        }
    }
}

// ---------------------------------------------------------------------------
extern "C" void kernel_launch(void* const* d_in, const int* in_sizes, int n_in,
                              void* d_out, int out_size)
{
    const float* x   = (const float*)d_in[0];
    const int*   eit = (const int*)d_in[1];
    const int*   eig = (const int*)d_in[2];
    const float* Wt1 = (const float*)d_in[3];
    const float* bt1 = (const float*)d_in[4];
    const float* Wt2 = (const float*)d_in[5];
    const float* bt2 = (const float*)d_in[6];
    const float* Wg1 = (const float*)d_in[7];
    const float* bg1 = (const float*)d_in[8];
    const float* Wg2 = (const float*)d_in[9];
    const float* bg2 = (const float*)d_in[10];
    const float* Wf  = (const float*)d_in[11];
    const float* bf  = (const float*)d_in[12];
    float* out = (float*)d_out;

    const int nN = in_sizes[0] / 64;
    const int nE = in_sizes[1] / 2;

    void* poolPtr = nullptr;
    cudaGetSymbolAddress(&poolPtr, g_pool);
    cudaMemsetAsync(poolPtr, 0, sizeof(float) * 2 * (size_t)N_MAX * 64, 0);

    const int smemN = (64 * 260 + 128 * 68) * 4;
    cudaFuncSetAttribute(node_kernel,
                         cudaFuncAttributeMaxDynamicSharedMemorySize, smemN);
    node_kernel<<<(nN + 127) / 128, 512, smemN>>>(x, Wt1, Wg1, bt1, bg1, nN);

    const int smemB = (4608 + BWARPS * 4608) * 2;   // 101376 B per CTA
    cudaFuncSetAttribute(branch_kernel,
                         cudaFuncAttributeMaxDynamicSharedMemorySize, smemB);
    dim3 gridB(148, 2);
    branch_kernel<<<gridB, 32 * BWARPS, smemB>>>(eit, eig, Wt2, Wg2, bt2, bg2, nE);

    const int smemF = (128 * 64 + 128 * 132) * 4;
    cudaFuncSetAttribute(final_kernel,
                         cudaFuncAttributeMaxDynamicSharedMemorySize, smemF);
    final_kernel<<<(nN + 127) / 128, 256, smemF>>>(Wf, bf, out, nN);
}

// round 13
// speedup vs baseline: 1.3807x; 1.1840x over previous
#include <cuda_runtime.h>
#include <cuda_fp16.h>
#include <cstdint>

// GMEdgeConv, fp16 storage + fp16 mma.sync edge GEMM, occupancy-first:
//   Stage 1 (node_kernel, fp32 math): g_UVh[n] = fp16([x@(Wt1a-Wt1b) | x@Wt1b+bt1 | x@(Wg1a-Wg1b) | x@Wg1b+bg1])
//   Stage 2 (branch_kernel): 10 warps/CTA, 3 CTAs/SM (30 warps/SM); per warp,
//       16-edge chunks: coalesced LDG gather, h1 = relu(U+V') combined in REGISTERS,
//       single h1 tile in SMEM (2304B/warp), D = h1 @ W2 via mma.m16n8k16.f16,
//       epilogue relu(D + b2) + zero-skip + filtered atomicMax segment pooling.
//   Stage 3 (final_kernel, fp32): out = relu([pool_t|pool_g] @ Wf + bf)

#define N_MAX 100000

__device__ float  g_pool[2][(size_t)N_MAX * 64];
__device__ __half g_UVh[(size_t)N_MAX * 256];

// D += A(16x16 f16) @ B(16x8 f16), fp32 accum
__device__ __forceinline__ void mma_f16(float* c, const uint32_t* a,
                                        uint32_t b0, uint32_t b1) {
    asm volatile(
        "mma.sync.aligned.m16n8k16.row.col.f32.f16.f16.f32 "
        "{%0,%1,%2,%3}, {%4,%5,%6,%7}, {%8,%9}, {%0,%1,%2,%3};\n"
        : "+f"(c[0]), "+f"(c[1]), "+f"(c[2]), "+f"(c[3])
        : "r"(a[0]), "r"(a[1]), "r"(a[2]), "r"(a[3]), "r"(b0), "r"(b1));
}

__device__ __forceinline__ uint32_t hrelu_add(uint32_t u, uint32_t v) {
    __half2 z = __float2half2_rn(0.f);
    __half2 r = __hmax2(__hadd2(*(__half2*)&u, *(__half2*)&v), z);
    return *(uint32_t*)&r;
}

// ---------------------------------------------------------------------------
// Stage 1: node projections (fp32 math, fp16 store), b1 folded into V columns.
// ---------------------------------------------------------------------------
__global__ __launch_bounds__(512, 1)
void node_kernel(const float* __restrict__ x,
                 const float* __restrict__ Wt1, const float* __restrict__ Wg1,
                 const float* __restrict__ bt1, const float* __restrict__ bg1,
                 int nN)
{
    extern __shared__ float sm[];
    float* Wc = sm;              // 64 x 260 (cols: Ut|Vt|Ug|Vg)
    float* As = Wc + 64 * 260;   // 128 x 68

    const int tid = threadIdx.x;
    const int tx  = tid & 31;
    const int ty  = tid >> 5;

    for (int idx = tid; idx < 64 * 256; idx += 512) {
        int k = idx >> 8, c = idx & 255;
        float v;
        if (c < 64)        v = Wt1[k * 64 + c] - Wt1[(64 + k) * 64 + c];
        else if (c < 128)  v = Wt1[(64 + k) * 64 + (c - 64)];
        else if (c < 192)  v = Wg1[k * 64 + (c - 128)] - Wg1[(64 + k) * 64 + (c - 128)];
        else               v = Wg1[(64 + k) * 64 + (c - 192)];
        Wc[k * 260 + c] = v;
    }

    const int base = blockIdx.x * 128;
    for (int idx = tid; idx < 128 * 16; idx += 512) {
        int nd = idx >> 4, q = idx & 15;
        float4 v = make_float4(0.f, 0.f, 0.f, 0.f);
        if (base + nd < nN) v = *(const float4*)(x + (size_t)(base + nd) * 64 + 4 * q);
        *(float4*)(As + nd * 68 + 4 * q) = v;
    }
    __syncthreads();

    #pragma unroll
    for (int p = 0; p < 2; p++) {
        const int c = p * 128 + 4 * tx;
        float acc[8][4];
        #pragma unroll
        for (int ii = 0; ii < 8; ii++)
            #pragma unroll
            for (int j = 0; j < 4; j++) acc[ii][j] = 0.f;

        #pragma unroll 4
        for (int k = 0; k < 64; k += 4) {
            float4 w0 = *(const float4*)(Wc + (k + 0) * 260 + c);
            float4 w1 = *(const float4*)(Wc + (k + 1) * 260 + c);
            float4 w2 = *(const float4*)(Wc + (k + 2) * 260 + c);
            float4 w3 = *(const float4*)(Wc + (k + 3) * 260 + c);
            #pragma unroll
            for (int ii = 0; ii < 8; ii++) {
                float4 a = *(const float4*)(As + (8 * ty + ii) * 68 + k);
                acc[ii][0] += a.x * w0.x + a.y * w1.x + a.z * w2.x + a.w * w3.x;
                acc[ii][1] += a.x * w0.y + a.y * w1.y + a.z * w2.y + a.w * w3.y;
                acc[ii][2] += a.x * w0.z + a.y * w1.z + a.z * w2.z + a.w * w3.z;
                acc[ii][3] += a.x * w0.w + a.y * w1.w + a.z * w2.w + a.w * w3.w;
            }
        }
        float4 bv = make_float4(0.f, 0.f, 0.f, 0.f);
        if (4 * tx >= 64) {
            const float* bp = (p ? bg1 : bt1) + (4 * tx - 64);
            bv = *(const float4*)bp;
        }
        #pragma unroll
        for (int ii = 0; ii < 8; ii++) {
            int node = base + 8 * ty + ii;
            if (node < nN) {
                __half2 h0 = __float22half2_rn(make_float2(acc[ii][0] + bv.x,
                                                           acc[ii][1] + bv.y));
                __half2 h1 = __float22half2_rn(make_float2(acc[ii][2] + bv.z,
                                                           acc[ii][3] + bv.w));
                uint2 pk;
                pk.x = *(uint32_t*)&h0;
                pk.y = *(uint32_t*)&h1;
                *(uint2*)(g_UVh + (size_t)node * 256 + c) = pk;
            }
        }
    }
}

// ---------------------------------------------------------------------------
// Stage 2: warp-level fp16 MMA edge GEMM + segment max, 30 warps/SM.
// grid (222, 2): y = branch. 3 CTAs/SM, 10 warps/CTA, warp = 16-edge chunk.
// smem/CTA (static): W2T 9216B + b2s 256B + 10 x h1 tile 2304B = 32512B.
// ---------------------------------------------------------------------------
#define BWARPS 10
__global__ __launch_bounds__(32 * BWARPS, 3)
void branch_kernel(const int* __restrict__ ei_t, const int* __restrict__ ei_g,
                   const float* __restrict__ Wt2, const float* __restrict__ Wg2,
                   const float* __restrict__ bt2, const float* __restrict__ bg2,
                   int nE)
{
    __shared__ __align__(16) __half W2T[64 * 72];          // [n][k], stride 72
    __shared__ float b2s[64];
    __shared__ __align__(16) __half Hs[BWARPS][16 * 72];   // per-warp h1, stride 72

    const int tid  = threadIdx.x;
    const int warp = tid >> 5;
    const int lane = tid & 31;
    const int qr   = lane & 3;      // threadID_in_group
    const int gp   = lane >> 2;     // groupID
    const int br   = blockIdx.y;

    const int*   ei = br ? ei_g : ei_t;
    const float* W2 = br ? Wg2 : Wt2;
    const float* b2 = br ? bg2 : bt2;
    float* pool = g_pool[br];

    // Stage W2^T: W2 is [k][n] row-major; store W2T[n*72 + k] (fp16).
    for (int idx = tid; idx < 64 * 64; idx += 32 * BWARPS) {
        int k = idx >> 6, n = idx & 63;
        W2T[n * 72 + k] = __float2half_rn(W2[idx]);
    }
    if (tid < 64) b2s[tid] = b2[tid];
    __syncthreads();

    const uint32_t* W2T32 = (const uint32_t*)W2T;
    uint32_t* Hw32 = (uint32_t*)Hs[warp];                  // row stride 36 words
    __half*   Hsw  = Hs[warp];

    const int grow = lane >> 3;     // row-group within coalesced LDG
    const int qb   = lane & 7;      // 16B chunk within 128B row

    const int nChunks = (nE + 15) >> 4;
    const int STRIDE = gridDim.x * BWARPS;

    for (int ch = blockIdx.x * BWARPS + warp; ch < nChunks; ch += STRIDE) {
        const int e0 = ch << 4;

        int iv;  // lanes 0..15: i of edge (lane); lanes 16..31: j of edge (lane-16)
        if (lane < 16) iv = (e0 + lane < nE) ? __ldcs(ei + e0 + lane) : -1;
        else           iv = (e0 + lane - 16 < nE) ? __ldcs(ei + nE + e0 + lane - 16) : 0;

        // ---- coalesced gather + combine h1 = relu(U[i]+V'[j]) in regs -> STS ----
        // Per gg: 8 lanes (qb) cover one full 128B row; 4 rows (grow) per LDG.
        #pragma unroll
        for (int gg = 0; gg < 4; gg++) {
            int e = gg * 4 + grow;
            int i = __shfl_sync(0xFFFFFFFFu, iv, e);
            int j = __shfl_sync(0xFFFFFFFFu, iv, e + 16);
            uint4 u = make_uint4(0u, 0u, 0u, 0u);
            uint4 v = make_uint4(0u, 0u, 0u, 0u);
            if (i >= 0) {
                u = *(const uint4*)(g_UVh + (size_t)i * 256 + br * 128 + qb * 8);
                v = *(const uint4*)(g_UVh + (size_t)j * 256 + br * 128 + 64 + qb * 8);
            }
            uint4 h;   // relu(0+0)=0 handles invalid edges
            h.x = hrelu_add(u.x, v.x);
            h.y = hrelu_add(u.y, v.y);
            h.z = hrelu_add(u.z, v.z);
            h.w = hrelu_add(u.w, v.w);
            *(uint4*)(Hsw + e * 72 + qb * 8) = h;
        }
        __syncwarp();

        // ---- D[16x64] = h1 @ W2 via 4x8 m16n8k16 f16 MMAs ----
        float acc[8][4];
        #pragma unroll
        for (int nt = 0; nt < 8; nt++)
            #pragma unroll
            for (int q = 0; q < 4; q++) acc[nt][q] = 0.f;

        #pragma unroll
        for (int kt = 0; kt < 4; kt++) {
            const int c = kt * 8 + qr;
            uint32_t a[4];
            a[0] = Hw32[gp * 36 + c];
            a[1] = Hw32[(gp + 8) * 36 + c];
            a[2] = Hw32[gp * 36 + c + 4];
            a[3] = Hw32[(gp + 8) * 36 + c + 4];
            #pragma unroll
            for (int nt = 0; nt < 8; nt++) {
                uint32_t b0 = W2T32[(nt * 8 + gp) * 36 + kt * 8 + qr];
                uint32_t b1 = W2T32[(nt * 8 + gp) * 36 + kt * 8 + qr + 4];
                mma_f16(acc[nt], a, b0, b1);
            }
        }
        __syncwarp();   // all Hs reads done before next chunk's STS

        // ---- epilogue: relu(D + b2), zero-skip + filtered segment-max ----
        int i1 = __shfl_sync(0xFFFFFFFFu, iv, gp);       // edge gp
        int i2 = __shfl_sync(0xFFFFFFFFu, iv, gp + 8);   // edge gp+8
        if (i1 >= 0) {
            float* pr = pool + (size_t)i1 * 64 + qr * 2;
            #pragma unroll
            for (int nt = 0; nt < 8; nt++) {
                float2 bb = *(const float2*)(b2s + nt * 8 + qr * 2);  // LDS bcast
                float va = fmaxf(acc[nt][0] + bb.x, 0.f);
                float vb = fmaxf(acc[nt][1] + bb.y, 0.f);
                if (va > 0.f || vb > 0.f) {   // pool >= 0: zero never wins
                    float2 cur = __ldcg((const float2*)(pr + nt * 8));
                    // pool only grows; stale read >= v proves final max >= v.
                    if (va > cur.x) atomicMax((int*)(pr + nt * 8),     __float_as_int(va));
                    if (vb > cur.y) atomicMax((int*)(pr + nt * 8 + 1), __float_as_int(vb));
                }
            }
        }
        if (i2 >= 0) {
            float* pr = pool + (size_t)i2 * 64 + qr * 2;
            #pragma unroll
            for (int nt = 0; nt < 8; nt++) {
                float2 bb = *(const float2*)(b2s + nt * 8 + qr * 2);
                float va = fmaxf(acc[nt][2] + bb.x, 0.f);
                float vb = fmaxf(acc[nt][3] + bb.y, 0.f);
                if (va > 0.f || vb > 0.f) {
                    float2 cur = __ldcg((const float2*)(pr + nt * 8));
                    if (va > cur.x) atomicMax((int*)(pr + nt * 8),     __float_as_int(va));
                    if (vb > cur.y) atomicMax((int*)(pr + nt * 8 + 1), __float_as_int(vb));
                }
            }
        }
    }
}

// ---------------------------------------------------------------------------
// Stage 3: out = relu([pool_t | pool_g] @ Wf + bf)   (fp32)
// ---------------------------------------------------------------------------
__global__ __launch_bounds__(256, 1)
void final_kernel(const float* __restrict__ Wf, const float* __restrict__ bf,
                  float* __restrict__ out, int nN)
{
    extern __shared__ float sm[];
    float* Wfs = sm;                // 128 x 64
    float* Ns  = Wfs + 128 * 64;    // 128 x 132

    const int tid = threadIdx.x;
    const int tx  = tid & 15;
    const int ty  = tid >> 4;

    for (int idx = tid; idx < 128 * 64; idx += 256) Wfs[idx] = Wf[idx];
    const float4 bfv = *(const float4*)(bf + 4 * tx);

    const int base = blockIdx.x * 128;
    for (int idx = tid; idx < 128 * 16; idx += 256) {
        int nd = idx >> 4, q = idx & 15;
        float4 a = make_float4(0.f, 0.f, 0.f, 0.f);
        float4 b = make_float4(0.f, 0.f, 0.f, 0.f);
        if (base + nd < nN) {
            a = *(const float4*)(g_pool[0] + (size_t)(base + nd) * 64 + 4 * q);
            b = *(const float4*)(g_pool[1] + (size_t)(base + nd) * 64 + 4 * q);
        }
        *(float4*)(Ns + nd * 132 + 4 * q) = a;
        *(float4*)(Ns + nd * 132 + 64 + 4 * q) = b;
    }
    __syncthreads();

    float acc[8][4];
    #pragma unroll
    for (int ii = 0; ii < 8; ii++)
        #pragma unroll
        for (int j = 0; j < 4; j++) acc[ii][j] = 0.f;

    #pragma unroll 4
    for (int k = 0; k < 128; k += 4) {
        float4 w0 = *(const float4*)(Wfs + (k + 0) * 64 + 4 * tx);
        float4 w1 = *(const float4*)(Wfs + (k + 1) * 64 + 4 * tx);
        float4 w2 = *(const float4*)(Wfs + (k + 2) * 64 + 4 * tx);
        float4 w3 = *(const float4*)(Wfs + (k + 3) * 64 + 4 * tx);
        #pragma unroll
        for (int ii = 0; ii < 8; ii++) {
            float4 a = *(const float4*)(Ns + (8 * ty + ii) * 132 + k);
            acc[ii][0] += a.x * w0.x + a.y * w1.x + a.z * w2.x + a.w * w3.x;
            acc[ii][1] += a.x * w0.y + a.y * w1.y + a.z * w2.y + a.w * w3.y;
            acc[ii][2] += a.x * w0.z + a.y * w1.z + a.z * w2.z + a.w * w3.z;
            acc[ii][3] += a.x * w0.w + a.y * w1.w + a.z * w2.w + a.w * w3.w;
        }
    }

    #pragma unroll
    for (int ii = 0; ii < 8; ii++) {
        int node = base + 8 * ty + ii;
        if (node < nN) {
            float4 o;
            o.x = fmaxf(acc[ii][0] + bfv.x, 0.f);
            o.y = fmaxf(acc[ii][1] + bfv.y, 0.f);
            o.z = fmaxf(acc[ii][2] + bfv.z, 0.f);
            o.w = fmaxf(acc[ii][3] + bfv.w, 0.f);
            *(float4*)(out + (size_t)node * 64 + 4 * tx) = o;
        }
    }
}

// ---------------------------------------------------------------------------
extern "C" void kernel_launch(void* const* d_in, const int* in_sizes, int n_in,
                              void* d_out, int out_size)
{
    const float* x   = (const float*)d_in[0];
    const int*   eit = (const int*)d_in[1];
    const int*   eig = (const int*)d_in[2];
    const float* Wt1 = (const float*)d_in[3];
    const float* bt1 = (const float*)d_in[4];
    const float* Wt2 = (const float*)d_in[5];
    const float* bt2 = (const float*)d_in[6];
    const float* Wg1 = (const float*)d_in[7];
    const float* bg1 = (const float*)d_in[8];
    const float* Wg2 = (const float*)d_in[9];
    const float* bg2 = (const float*)d_in[10];
    const float* Wf  = (const float*)d_in[11];
    const float* bf  = (const float*)d_in[12];
    float* out = (float*)d_out;

    const int nN = in_sizes[0] / 64;
    const int nE = in_sizes[1] / 2;

    void* poolPtr = nullptr;
    cudaGetSymbolAddress(&poolPtr, g_pool);
    cudaMemsetAsync(poolPtr, 0, sizeof(float) * 2 * (size_t)N_MAX * 64, 0);

    const int smemN = (64 * 260 + 128 * 68) * 4;
    cudaFuncSetAttribute(node_kernel,
                         cudaFuncAttributeMaxDynamicSharedMemorySize, smemN);
    node_kernel<<<(nN + 127) / 128, 512, smemN>>>(x, Wt1, Wg1, bt1, bg1, nN);

    dim3 gridB(222, 2);   // 444 CTAs = 3 per SM
    branch_kernel<<<gridB, 32 * BWARPS>>>(eit, eig, Wt2, Wg2, bt2, bg2, nE);

    const int smemF = (128 * 64 + 128 * 132) * 4;
    cudaFuncSetAttribute(final_kernel,
                         cudaFuncAttributeMaxDynamicSharedMemorySize, smemF);
    final_kernel<<<(nN + 127) / 128, 256, smemF>>>(Wf, bf, out, nN);
}

// round 14
// speedup vs baseline: 1.3923x; 1.0084x over previous
#include <cuda_runtime.h>
#include <cuda_fp16.h>
#include <cstdint>

// GMEdgeConv, fp16 storage + fp16 mma.sync edge GEMM, occupancy-first,
// branches run SEQUENTIALLY so each phase's working set (UV half 25.6MB +
// pool half 25.6MB + edges 12.8MB = 64MB) is L2-resident (126MB L2).
//   Stage 1 (node_kernel, fp32 math): g_UVh[n] = fp16([x@(Wt1a-Wt1b) | x@Wt1b+bt1 | x@(Wg1a-Wg1b) | x@Wg1b+bg1])
//   Stage 2 (branch_kernel x2): 10 warps/CTA, 3 CTAs/SM (30 warps/SM); per warp,
//       16-edge chunks: coalesced LDG gather, h1 = relu(U+V') combined in registers,
//       single h1 tile in SMEM (2304B/warp), D = h1 @ W2 via mma.m16n8k16.f16,
//       epilogue relu(D + b2) + zero-skip + filtered atomicMax segment pooling.
//   Stage 3 (final_kernel, fp32): out = relu([pool_t|pool_g] @ Wf + bf)

#define N_MAX 100000

__device__ float  g_pool[2][(size_t)N_MAX * 64];
__device__ __half g_UVh[(size_t)N_MAX * 256];

// D += A(16x16 f16) @ B(16x8 f16), fp32 accum
__device__ __forceinline__ void mma_f16(float* c, const uint32_t* a,
                                        uint32_t b0, uint32_t b1) {
    asm volatile(
        "mma.sync.aligned.m16n8k16.row.col.f32.f16.f16.f32 "
        "{%0,%1,%2,%3}, {%4,%5,%6,%7}, {%8,%9}, {%0,%1,%2,%3};\n"
        : "+f"(c[0]), "+f"(c[1]), "+f"(c[2]), "+f"(c[3])
        : "r"(a[0]), "r"(a[1]), "r"(a[2]), "r"(a[3]), "r"(b0), "r"(b1));
}

__device__ __forceinline__ uint32_t hrelu_add(uint32_t u, uint32_t v) {
    __half2 z = __float2half2_rn(0.f);
    __half2 r = __hmax2(__hadd2(*(__half2*)&u, *(__half2*)&v), z);
    return *(uint32_t*)&r;
}

// ---------------------------------------------------------------------------
// Stage 1: node projections (fp32 math, fp16 store), b1 folded into V columns.
// ---------------------------------------------------------------------------
__global__ __launch_bounds__(512, 1)
void node_kernel(const float* __restrict__ x,
                 const float* __restrict__ Wt1, const float* __restrict__ Wg1,
                 const float* __restrict__ bt1, const float* __restrict__ bg1,
                 int nN)
{
    extern __shared__ float sm[];
    float* Wc = sm;              // 64 x 260 (cols: Ut|Vt|Ug|Vg)
    float* As = Wc + 64 * 260;   // 128 x 68

    const int tid = threadIdx.x;
    const int tx  = tid & 31;
    const int ty  = tid >> 5;

    for (int idx = tid; idx < 64 * 256; idx += 512) {
        int k = idx >> 8, c = idx & 255;
        float v;
        if (c < 64)        v = Wt1[k * 64 + c] - Wt1[(64 + k) * 64 + c];
        else if (c < 128)  v = Wt1[(64 + k) * 64 + (c - 64)];
        else if (c < 192)  v = Wg1[k * 64 + (c - 128)] - Wg1[(64 + k) * 64 + (c - 128)];
        else               v = Wg1[(64 + k) * 64 + (c - 192)];
        Wc[k * 260 + c] = v;
    }

    const int base = blockIdx.x * 128;
    for (int idx = tid; idx < 128 * 16; idx += 512) {
        int nd = idx >> 4, q = idx & 15;
        float4 v = make_float4(0.f, 0.f, 0.f, 0.f);
        if (base + nd < nN) v = *(const float4*)(x + (size_t)(base + nd) * 64 + 4 * q);
        *(float4*)(As + nd * 68 + 4 * q) = v;
    }
    __syncthreads();

    #pragma unroll
    for (int p = 0; p < 2; p++) {
        const int c = p * 128 + 4 * tx;
        float acc[8][4];
        #pragma unroll
        for (int ii = 0; ii < 8; ii++)
            #pragma unroll
            for (int j = 0; j < 4; j++) acc[ii][j] = 0.f;

        #pragma unroll 4
        for (int k = 0; k < 64; k += 4) {
            float4 w0 = *(const float4*)(Wc + (k + 0) * 260 + c);
            float4 w1 = *(const float4*)(Wc + (k + 1) * 260 + c);
            float4 w2 = *(const float4*)(Wc + (k + 2) * 260 + c);
            float4 w3 = *(const float4*)(Wc + (k + 3) * 260 + c);
            #pragma unroll
            for (int ii = 0; ii < 8; ii++) {
                float4 a = *(const float4*)(As + (8 * ty + ii) * 68 + k);
                acc[ii][0] += a.x * w0.x + a.y * w1.x + a.z * w2.x + a.w * w3.x;
                acc[ii][1] += a.x * w0.y + a.y * w1.y + a.z * w2.y + a.w * w3.y;
                acc[ii][2] += a.x * w0.z + a.y * w1.z + a.z * w2.z + a.w * w3.z;
                acc[ii][3] += a.x * w0.w + a.y * w1.w + a.z * w2.w + a.w * w3.w;
            }
        }
        float4 bv = make_float4(0.f, 0.f, 0.f, 0.f);
        if (4 * tx >= 64) {
            const float* bp = (p ? bg1 : bt1) + (4 * tx - 64);
            bv = *(const float4*)bp;
        }
        #pragma unroll
        for (int ii = 0; ii < 8; ii++) {
            int node = base + 8 * ty + ii;
            if (node < nN) {
                __half2 h0 = __float22half2_rn(make_float2(acc[ii][0] + bv.x,
                                                           acc[ii][1] + bv.y));
                __half2 h1 = __float22half2_rn(make_float2(acc[ii][2] + bv.z,
                                                           acc[ii][3] + bv.w));
                uint2 pk;
                pk.x = *(uint32_t*)&h0;
                pk.y = *(uint32_t*)&h1;
                *(uint2*)(g_UVh + (size_t)node * 256 + c) = pk;
            }
        }
    }
}

// ---------------------------------------------------------------------------
// Stage 2: warp-level fp16 MMA edge GEMM + segment max, 30 warps/SM.
// Launched ONCE PER BRANCH (sequential, L2-resident working set per phase).
// grid (444): 3 CTAs/SM, 10 warps/CTA, warp = 16-edge chunk.
// smem/CTA (static): W2T 9216B + b2s 256B + 10 x h1 tile 2304B = 32512B.
// ---------------------------------------------------------------------------
#define BWARPS 10
__global__ __launch_bounds__(32 * BWARPS, 3)
void branch_kernel(const int* __restrict__ ei,
                   const float* __restrict__ W2, const float* __restrict__ b2,
                   int nE, int br)
{
    __shared__ __align__(16) __half W2T[64 * 72];          // [n][k], stride 72
    __shared__ float b2s[64];
    __shared__ __align__(16) __half Hs[BWARPS][16 * 72];   // per-warp h1, stride 72

    const int tid  = threadIdx.x;
    const int warp = tid >> 5;
    const int lane = tid & 31;
    const int qr   = lane & 3;      // threadID_in_group
    const int gp   = lane >> 2;     // groupID

    float* pool = g_pool[br];

    // Stage W2^T: W2 is [k][n] row-major; store W2T[n*72 + k] (fp16).
    for (int idx = tid; idx < 64 * 64; idx += 32 * BWARPS) {
        int k = idx >> 6, n = idx & 63;
        W2T[n * 72 + k] = __float2half_rn(W2[idx]);
    }
    if (tid < 64) b2s[tid] = b2[tid];
    __syncthreads();

    const uint32_t* W2T32 = (const uint32_t*)W2T;
    uint32_t* Hw32 = (uint32_t*)Hs[warp];                  // row stride 36 words
    __half*   Hsw  = Hs[warp];

    const int grow = lane >> 3;     // row-group within coalesced LDG
    const int qb   = lane & 7;      // 16B chunk within 128B row

    const int nChunks = (nE + 15) >> 4;
    const int STRIDE = gridDim.x * BWARPS;

    for (int ch = blockIdx.x * BWARPS + warp; ch < nChunks; ch += STRIDE) {
        const int e0 = ch << 4;

        int iv;  // lanes 0..15: i of edge (lane); lanes 16..31: j of edge (lane-16)
        if (lane < 16) iv = (e0 + lane < nE) ? __ldcs(ei + e0 + lane) : -1;
        else           iv = (e0 + lane - 16 < nE) ? __ldcs(ei + nE + e0 + lane - 16) : 0;

        // ---- coalesced gather + combine h1 = relu(U[i]+V'[j]) in regs -> STS ----
        // Per gg: 8 lanes (qb) cover one full 128B row; 4 rows (grow) per LDG.
        #pragma unroll
        for (int gg = 0; gg < 4; gg++) {
            int e = gg * 4 + grow;
            int i = __shfl_sync(0xFFFFFFFFu, iv, e);
            int j = __shfl_sync(0xFFFFFFFFu, iv, e + 16);
            uint4 u = make_uint4(0u, 0u, 0u, 0u);
            uint4 v = make_uint4(0u, 0u, 0u, 0u);
            if (i >= 0) {
                u = *(const uint4*)(g_UVh + (size_t)i * 256 + br * 128 + qb * 8);
                v = *(const uint4*)(g_UVh + (size_t)j * 256 + br * 128 + 64 + qb * 8);
            }
            uint4 h;   // relu(0+0)=0 handles invalid edges
            h.x = hrelu_add(u.x, v.x);
            h.y = hrelu_add(u.y, v.y);
            h.z = hrelu_add(u.z, v.z);
            h.w = hrelu_add(u.w, v.w);
            *(uint4*)(Hsw + e * 72 + qb * 8) = h;
        }
        __syncwarp();

        // ---- D[16x64] = h1 @ W2 via 4x8 m16n8k16 f16 MMAs ----
        float acc[8][4];
        #pragma unroll
        for (int nt = 0; nt < 8; nt++)
            #pragma unroll
            for (int q = 0; q < 4; q++) acc[nt][q] = 0.f;

        #pragma unroll
        for (int kt = 0; kt < 4; kt++) {
            const int c = kt * 8 + qr;
            uint32_t a[4];
            a[0] = Hw32[gp * 36 + c];
            a[1] = Hw32[(gp + 8) * 36 + c];
            a[2] = Hw32[gp * 36 + c + 4];
            a[3] = Hw32[(gp + 8) * 36 + c + 4];
            #pragma unroll
            for (int nt = 0; nt < 8; nt++) {
                uint32_t b0 = W2T32[(nt * 8 + gp) * 36 + kt * 8 + qr];
                uint32_t b1 = W2T32[(nt * 8 + gp) * 36 + kt * 8 + qr + 4];
                mma_f16(acc[nt], a, b0, b1);
            }
        }
        __syncwarp();   // all Hs reads done before next chunk's STS

        // ---- epilogue: relu(D + b2), zero-skip + filtered segment-max ----
        int i1 = __shfl_sync(0xFFFFFFFFu, iv, gp);       // edge gp
        int i2 = __shfl_sync(0xFFFFFFFFu, iv, gp + 8);   // edge gp+8
        if (i1 >= 0) {
            float* pr = pool + (size_t)i1 * 64 + qr * 2;
            #pragma unroll
            for (int nt = 0; nt < 8; nt++) {
                float2 bb = *(const float2*)(b2s + nt * 8 + qr * 2);  // LDS bcast
                float va = fmaxf(acc[nt][0] + bb.x, 0.f);
                float vb = fmaxf(acc[nt][1] + bb.y, 0.f);
                if (va > 0.f || vb > 0.f) {   // pool >= 0: zero never wins
                    float2 cur = __ldcg((const float2*)(pr + nt * 8));
                    // pool only grows; stale read >= v proves final max >= v.
                    if (va > cur.x) atomicMax((int*)(pr + nt * 8),     __float_as_int(va));
                    if (vb > cur.y) atomicMax((int*)(pr + nt * 8 + 1), __float_as_int(vb));
                }
            }
        }
        if (i2 >= 0) {
            float* pr = pool + (size_t)i2 * 64 + qr * 2;
            #pragma unroll
            for (int nt = 0; nt < 8; nt++) {
                float2 bb = *(const float2*)(b2s + nt * 8 + qr * 2);
                float va = fmaxf(acc[nt][2] + bb.x, 0.f);
                float vb = fmaxf(acc[nt][3] + bb.y, 0.f);
                if (va > 0.f || vb > 0.f) {
                    float2 cur = __ldcg((const float2*)(pr + nt * 8));
                    if (va > cur.x) atomicMax((int*)(pr + nt * 8),     __float_as_int(va));
                    if (vb > cur.y) atomicMax((int*)(pr + nt * 8 + 1), __float_as_int(vb));
                }
            }
        }
    }
}

// ---------------------------------------------------------------------------
// Stage 3: out = relu([pool_t | pool_g] @ Wf + bf)   (fp32)
// ---------------------------------------------------------------------------
__global__ __launch_bounds__(256, 1)
void final_kernel(const float* __restrict__ Wf, const float* __restrict__ bf,
                  float* __restrict__ out, int nN)
{
    extern __shared__ float sm[];
    float* Wfs = sm;                // 128 x 64
    float* Ns  = Wfs + 128 * 64;    // 128 x 132

    const int tid = threadIdx.x;
    const int tx  = tid & 15;
    const int ty  = tid >> 4;

    for (int idx = tid; idx < 128 * 64; idx += 256) Wfs[idx] = Wf[idx];
    const float4 bfv = *(const float4*)(bf + 4 * tx);

    const int base = blockIdx.x * 128;
    for (int idx = tid; idx < 128 * 16; idx += 256) {
        int nd = idx >> 4, q = idx & 15;
        float4 a = make_float4(0.f, 0.f, 0.f, 0.f);
        float4 b = make_float4(0.f, 0.f, 0.f, 0.f);
        if (base + nd < nN) {
            a = *(const float4*)(g_pool[0] + (size_t)(base + nd) * 64 + 4 * q);
            b = *(const float4*)(g_pool[1] + (size_t)(base + nd) * 64 + 4 * q);
        }
        *(float4*)(Ns + nd * 132 + 4 * q) = a;
        *(float4*)(Ns + nd * 132 + 64 + 4 * q) = b;
    }
    __syncthreads();

    float acc[8][4];
    #pragma unroll
    for (int ii = 0; ii < 8; ii++)
        #pragma unroll
        for (int j = 0; j < 4; j++) acc[ii][j] = 0.f;

    #pragma unroll 4
    for (int k = 0; k < 128; k += 4) {
        float4 w0 = *(const float4*)(Wfs + (k + 0) * 64 + 4 * tx);
        float4 w1 = *(const float4*)(Wfs + (k + 1) * 64 + 4 * tx);
        float4 w2 = *(const float4*)(Wfs + (k + 2) * 64 + 4 * tx);
        float4 w3 = *(const float4*)(Wfs + (k + 3) * 64 + 4 * tx);
        #pragma unroll
        for (int ii = 0; ii < 8; ii++) {
            float4 a = *(const float4*)(Ns + (8 * ty + ii) * 132 + k);
            acc[ii][0] += a.x * w0.x + a.y * w1.x + a.z * w2.x + a.w * w3.x;
            acc[ii][1] += a.x * w0.y + a.y * w1.y + a.z * w2.y + a.w * w3.y;
            acc[ii][2] += a.x * w0.z + a.y * w1.z + a.z * w2.z + a.w * w3.z;
            acc[ii][3] += a.x * w0.w + a.y * w1.w + a.z * w2.w + a.w * w3.w;
        }
    }

    #pragma unroll
    for (int ii = 0; ii < 8; ii++) {
        int node = base + 8 * ty + ii;
        if (node < nN) {
            float4 o;
            o.x = fmaxf(acc[ii][0] + bfv.x, 0.f);
            o.y = fmaxf(acc[ii][1] + bfv.y, 0.f);
            o.z = fmaxf(acc[ii][2] + bfv.z, 0.f);
            o.w = fmaxf(acc[ii][3] + bfv.w, 0.f);
            *(float4*)(out + (size_t)node * 64 + 4 * tx) = o;
        }
    }
}

// ---------------------------------------------------------------------------
extern "C" void kernel_launch(void* const* d_in, const int* in_sizes, int n_in,
                              void* d_out, int out_size)
{
    const float* x   = (const float*)d_in[0];
    const int*   eit = (const int*)d_in[1];
    const int*   eig = (const int*)d_in[2];
    const float* Wt1 = (const float*)d_in[3];
    const float* bt1 = (const float*)d_in[4];
    const float* Wt2 = (const float*)d_in[5];
    const float* bt2 = (const float*)d_in[6];
    const float* Wg1 = (const float*)d_in[7];
    const float* bg1 = (const float*)d_in[8];
    const float* Wg2 = (const float*)d_in[9];
    const float* bg2 = (const float*)d_in[10];
    const float* Wf  = (const float*)d_in[11];
    const float* bf  = (const float*)d_in[12];
    float* out = (float*)d_out;

    const int nN = in_sizes[0] / 64;
    const int nE = in_sizes[1] / 2;

    void* poolPtr = nullptr;
    cudaGetSymbolAddress(&poolPtr, g_pool);
    cudaMemsetAsync(poolPtr, 0, sizeof(float) * 2 * (size_t)N_MAX * 64, 0);

    const int smemN = (64 * 260 + 128 * 68) * 4;
    cudaFuncSetAttribute(node_kernel,
                         cudaFuncAttributeMaxDynamicSharedMemorySize, smemN);
    node_kernel<<<(nN + 127) / 128, 512, smemN>>>(x, Wt1, Wg1, bt1, bg1, nN);

    // Sequential branch phases: each phase's working set is L2-resident.
    branch_kernel<<<444, 32 * BWARPS>>>(eit, Wt2, bt2, nE, 0);
    branch_kernel<<<444, 32 * BWARPS>>>(eig, Wg2, bg2, nE, 1);

    const int smemF = (128 * 64 + 128 * 132) * 4;
    cudaFuncSetAttribute(final_kernel,
                         cudaFuncAttributeMaxDynamicSharedMemorySize, smemF);
    final_kernel<<<(nN + 127) / 128, 256, smemF>>>(Wf, bf, out, nN);
}